// round 1
// baseline (speedup 1.0000x reference)
#include <cuda_runtime.h>
#include <cstdint>

// Problem constants
#define B_    16
#define CIN   64
#define CGRP  64      // channels per wavelet group == conv2 cout
#define H1    128
#define W1    128
#define H2    256
#define W2    256

// Tiling
#define TH      16      // output rows per CTA
#define TW      64      // output cols per CTA
#define THREADS 256
#define CICHUNK 16      // input channels resident in smem at a time
#define NCHUNK  (CIN / CICHUNK)
#define EOC     16      // effective output channels per CTA

// Smem x tile (stored as f32x2 pairs: pair[c] = {raw[c], raw[c+16]})
#define XROWS  (TH + 2)   // 18
#define XRAW   (TW + 2)   // 66 raw columns (with halo)
#define XPAIR  50         // pair entries actually used (tx+dx+32 <= 49)
#define XPITCH 56         // padded pair pitch

// 256 MiB scratch for the upsampled intermediate (allocation-free rule)
__device__ float g_up[(size_t)B_ * CGRP * H2 * W2];

__device__ __forceinline__ void fma2(unsigned long long &d, unsigned long long a, unsigned long long b) {
    asm("fma.rn.f32x2 %0, %1, %2, %0;" : "+l"(d) : "l"(a), "l"(b));
}
__device__ __forceinline__ float loF(unsigned long long v) { return __uint_as_float((unsigned)(v & 0xffffffffull)); }
__device__ __forceinline__ float hiF(unsigned long long v) { return __uint_as_float((unsigned)(v >> 32)); }

// CONV1: in = x (B,64,128,128), w = w_pre (256,64,3,3). Epilogue does the
//        wavelet 2x2 mixing and writes the upsampled image (B,64,256,256) to out.
// CONV2: in = g_up (B,64,256,256), w = w_post (64,64,3,3), writes final output.
template<bool CONV1>
__global__ void __launch_bounds__(THREADS, 1)
conv_kernel(const float* __restrict__ in,
            const float* __restrict__ wgt,
            const float* __restrict__ bias,
            float* __restrict__ out)
{
    const int Hin = CONV1 ? H1 : H2;
    const int Win = CONV1 ? W1 : W2;
    const int twTiles = Win / TW;

    extern __shared__ char smem_raw[];
    unsigned long long* sw = (unsigned long long*)smem_raw;          // [EOC][CIN][9] duplicated f32x2
    unsigned long long* sx = sw + EOC * CIN * 9;                     // [CICHUNK][XROWS][XPITCH] pairs

    const int tid = threadIdx.x;
    const int ty  = tid >> 4;   // 0..15 -> output row within tile
    const int tx  = tid & 15;   // 0..15 -> base col; thread covers cols tx + {0,16,32,48}

    const int bx  = blockIdx.x;
    const int twi = bx % twTiles;
    const int cch = bx / twTiles;      // output-channel chunk
    const int gh0 = blockIdx.y * TH;
    const int gw0 = twi * TW;
    const int b   = blockIdx.z;

    // ---- cooperative weight load (duplicate each scalar into both f32x2 halves) ----
    for (int i = tid; i < EOC * CIN * 9; i += THREADS) {
        int o = i / (CIN * 9);
        int r = i - o * (CIN * 9);     // ci*9 + tap
        int oc;
        if (CONV1) {
            int g  = o >> 2;           // wavelet group
            int cc = o & 3;            // c within this CTA's 4 channels
            oc = g * CGRP + cch * 4 + cc;
        } else {
            oc = cch * EOC + o;
        }
        unsigned int u = __float_as_uint(wgt[(size_t)oc * (CIN * 9) + r]);
        sw[i] = ((unsigned long long)u << 32) | u;
    }

    unsigned long long acc[EOC][2];
    #pragma unroll
    for (int o = 0; o < EOC; o++) { acc[o][0] = 0ull; acc[o][1] = 0ull; }

    for (int ch = 0; ch < NCHUNK; ch++) {
        __syncthreads();
        // ---- load x chunk into paired smem: pair[c] = {raw[c], raw[c+16]} ----
        const int NEL = CICHUNK * XROWS * XRAW;   // 19008
        for (int i = tid; i < NEL; i += THREADS) {
            int ci  = i / (XROWS * XRAW);
            int rem = i - ci * (XROWS * XRAW);
            int r   = rem / XRAW;
            int c   = rem - r * XRAW;
            int gy  = gh0 - 1 + r;
            int gx  = gw0 - 1 + c;
            float v = 0.0f;
            if (gy >= 0 && gy < Hin && gx >= 0 && gx < Win)
                v = in[(((size_t)b * CIN + (ch * CICHUNK + ci)) * Hin + gy) * Win + gx];
            float* prow = (float*)&sx[(ci * XROWS + r) * XPITCH];
            if (c < XPAIR) prow[2 * c]            = v;   // lo half of pair c
            if (c >= 16)   prow[2 * (c - 16) + 1] = v;   // hi half of pair c-16
        }
        __syncthreads();

        // ---- accumulate ----
        #pragma unroll 1
        for (int ci = 0; ci < CICHUNK; ci++) {
            const unsigned long long* xr = &sx[(ci * XROWS + ty) * XPITCH + tx];
            const unsigned long long* wr = &sw[(ch * CICHUNK + ci) * 9];
            #pragma unroll
            for (int dy = 0; dy < 3; dy++) {
                #pragma unroll
                for (int dx = 0; dx < 3; dx++) {
                    unsigned long long xa = xr[dy * XPITCH + dx];        // pixels (tx, tx+16)
                    unsigned long long xb = xr[dy * XPITCH + dx + 32];   // pixels (tx+32, tx+48)
                    #pragma unroll
                    for (int o = 0; o < EOC; o++) {
                        unsigned long long wv = wr[(size_t)o * (CIN * 9) + dy * 3 + dx];
                        fma2(acc[o][0], xa, wv);
                        fma2(acc[o][1], xb, wv);
                    }
                }
            }
        }
    }

    // ---- epilogue ----
    if (CONV1) {
        #pragma unroll
        for (int cc = 0; cc < 4; cc++) {
            int c = cch * 4 + cc;
            float bll = bias[0 * CGRP + c];
            float blh = bias[1 * CGRP + c];
            float bhl = bias[2 * CGRP + c];
            float bhh = bias[3 * CGRP + c];
            #pragma unroll
            for (int pr = 0; pr < 2; pr++) {
                #pragma unroll
                for (int hp = 0; hp < 2; hp++) {
                    float ll = (hp ? hiF(acc[0 * 4 + cc][pr]) : loF(acc[0 * 4 + cc][pr])) + bll;
                    float lh = (hp ? hiF(acc[1 * 4 + cc][pr]) : loF(acc[1 * 4 + cc][pr])) + blh;
                    float hl = (hp ? hiF(acc[2 * 4 + cc][pr]) : loF(acc[2 * 4 + cc][pr])) + bhl;
                    float hh = (hp ? hiF(acc[3 * 4 + cc][pr]) : loF(acc[3 * 4 + cc][pr])) + bhh;
                    float ee = 0.5f * (ll + lh + hl + hh);
                    float eo = 0.5f * (ll - lh + hl - hh);
                    float oe = 0.5f * (ll + lh - hl - hh);
                    float oo = 0.5f * (ll - lh - hl + hh);
                    int sbrow = gh0 + ty;
                    int sbcol = gw0 + tx + 16 * (hp + 2 * pr);
                    size_t base = (((size_t)b * CGRP + c) * H2 + 2 * sbrow) * W2 + 2 * sbcol;
                    *(float2*)&out[base]      = make_float2(ee, eo);   // row 2h+0: {ee, eo}
                    *(float2*)&out[base + W2] = make_float2(oe, oo);   // row 2h+1: {oe, oo}
                }
            }
        }
    } else {
        #pragma unroll
        for (int o = 0; o < EOC; o++) {
            int c = cch * EOC + o;
            float bv = bias[c];
            size_t rowbase = (((size_t)b * CGRP + c) * H2 + (gh0 + ty)) * W2 + gw0;
            #pragma unroll
            for (int pr = 0; pr < 2; pr++) {
                #pragma unroll
                for (int hp = 0; hp < 2; hp++) {
                    float v = (hp ? hiF(acc[o][pr]) : loF(acc[o][pr])) + bv;
                    out[rowbase + tx + 16 * (hp + 2 * pr)] = v;
                }
            }
        }
    }
}

extern "C" void kernel_launch(void* const* d_in, const int* in_sizes, int n_in,
                              void* d_out, int out_size)
{
    const float* x      = (const float*)d_in[0];
    const float* w_pre  = (const float*)d_in[1];
    const float* b_pre  = (const float*)d_in[2];
    const float* w_post = (const float*)d_in[3];
    const float* b_post = (const float*)d_in[4];
    float* out = (float*)d_out;

    float* up = nullptr;
    cudaGetSymbolAddress((void**)&up, g_up);

    size_t smem = (size_t)(EOC * CIN * 9) * 8 + (size_t)CICHUNK * XROWS * XPITCH * 8;  // 202,752 B
    cudaFuncSetAttribute(conv_kernel<true>,  cudaFuncAttributeMaxDynamicSharedMemorySize, (int)smem);
    cudaFuncSetAttribute(conv_kernel<false>, cudaFuncAttributeMaxDynamicSharedMemorySize, (int)smem);

    dim3 blk(THREADS);
    // conv1: 2 col-tiles * 16 c-chunks, 8 row-tiles, 16 batches
    dim3 g1((W1 / TW) * (CGRP / 4), H1 / TH, B_);
    conv_kernel<true><<<g1, blk, smem>>>(x, w_pre, b_pre, up);
    // conv2: 4 col-tiles * 4 c-chunks, 16 row-tiles, 16 batches
    dim3 g2((W2 / TW) * (CGRP / EOC), H2 / TH, B_);
    conv_kernel<false><<<g2, blk, smem>>>(up, w_post, b_post, out);
}

// round 2
// speedup vs baseline: 1.1387x; 1.1387x over previous
#include <cuda_runtime.h>
#include <cstdint>

// Problem constants
#define B_    16
#define CIN   64
#define CGRP  64
#define H1    128
#define W1    128
#define H2    256
#define W2    256

// Tiling
#define TH      16       // output rows per CTA
#define TW      128      // output cols per CTA
#define THREADS 256
#define CICHUNK 4        // input channels resident in smem at a time
#define NCHUNK  (CIN / CICHUNK)
#define EOC     8        // effective output channels per CTA
#define NPAIR   4        // f32x2 pixel pairs per thread (8 pixels)

// Smem x tile: pair[c] = {raw[c], raw[c+16]}
#define XROWS   (TH + 2)    // 18
#define XRAW    (TW + 2)    // 130 raw cols incl. halo
#define XPAIRS  114         // pair slots (idx up to tx+dx+96 = 113)
#define XPITCH  116         // padded pair pitch (ULL units)

// scratch for the upsampled intermediate (allocation-free rule)
__device__ float g_up[(size_t)B_ * CGRP * H2 * W2];

__device__ __forceinline__ void fma2(unsigned long long &d, unsigned long long a, unsigned long long b) {
    asm("fma.rn.f32x2 %0, %1, %2, %0;" : "+l"(d) : "l"(a), "l"(b));
}
__device__ __forceinline__ float loF(unsigned long long v) { return __uint_as_float((unsigned)(v & 0xffffffffull)); }
__device__ __forceinline__ float hiF(unsigned long long v) { return __uint_as_float((unsigned)(v >> 32)); }

// CONV1: in = x (B,64,128,128), w = w_pre (256,64,3,3); epilogue does wavelet
//        2x2 mixing, writes upsampled (B,64,256,256) to out (= g_up).
// CONV2: in = g_up, w = w_post (64,64,3,3), writes final output.
template<bool CONV1>
__global__ void __launch_bounds__(THREADS, 2)
conv_kernel(const float* __restrict__ in,
            const float* __restrict__ wgt,
            const float* __restrict__ bias,
            float* __restrict__ out)
{
    const int Hin = CONV1 ? H1 : H2;
    const int Win = CONV1 ? W1 : W2;
    const int twTiles = Win / TW;

    extern __shared__ char smem_raw[];
    // weights: [CIN][9][EOC] duplicated f32x2  (o-contiguous for LDS.128 pairs)
    unsigned long long* sw = (unsigned long long*)smem_raw;               // 4608 ULL = 36,864 B
    unsigned long long* sx = sw + CIN * 9 * EOC;                          // [CICHUNK][XROWS][XPITCH]

    const int tid = threadIdx.x;
    const int ty  = tid >> 4;   // 0..15 output row in tile
    const int tx  = tid & 15;   // base col; thread covers cols tx + 16k, k=0..7

    const int bx  = blockIdx.x;
    const int twi = bx % twTiles;
    const int cch = bx / twTiles;
    const int gh0 = blockIdx.y * TH;
    const int gw0 = twi * TW;
    const int b   = blockIdx.z;

    // ---- weight load: sw[(ci*9 + tap)*EOC + o], each value duplicated in both halves ----
    for (int i = tid; i < CIN * 9 * EOC; i += THREADS) {
        int o   = i & (EOC - 1);
        int rem = i >> 3;            // ci*9 + tap
        int oc;
        if (CONV1) {
            int g  = o >> 1;         // wavelet group (0..3)
            int cc = o & 1;
            oc = g * CGRP + cch * 2 + cc;
        } else {
            oc = cch * EOC + o;
        }
        unsigned int u = __float_as_uint(wgt[(size_t)oc * (CIN * 9) + rem]);
        sw[i] = ((unsigned long long)u << 32) | u;
    }

    unsigned long long acc[EOC][NPAIR];
    #pragma unroll
    for (int o = 0; o < EOC; o++)
        #pragma unroll
        for (int p = 0; p < NPAIR; p++) acc[o][p] = 0ull;

    for (int ch = 0; ch < NCHUNK; ch++) {
        __syncthreads();
        // ---- load x chunk: pair[c] = {raw[c], raw[c+16]} ----
        const int NEL = CICHUNK * XROWS * XRAW;   // 9360
        for (int i = tid; i < NEL; i += THREADS) {
            int ci  = i / (XROWS * XRAW);
            int rem = i - ci * (XROWS * XRAW);
            int r   = rem / XRAW;
            int c   = rem - r * XRAW;
            int gy  = gh0 - 1 + r;
            int gx  = gw0 - 1 + c;
            float v = 0.0f;
            if (gy >= 0 && gy < Hin && gx >= 0 && gx < Win)
                v = in[(((size_t)b * CIN + (ch * CICHUNK + ci)) * Hin + gy) * Win + gx];
            float* prow = (float*)&sx[(ci * XROWS + r) * XPITCH];
            if (c < XPAIRS) prow[2 * c]            = v;
            if (c >= 16)    prow[2 * (c - 16) + 1] = v;
        }
        __syncthreads();

        #pragma unroll 1
        for (int ci = 0; ci < CICHUNK; ci++) {
            const unsigned long long* xr = &sx[(ci * XROWS + ty) * XPITCH + tx];
            const unsigned long long* wr = &sw[((ch * CICHUNK + ci) * 9) * EOC];
            #pragma unroll
            for (int dy = 0; dy < 3; dy++) {
                #pragma unroll
                for (int dx = 0; dx < 3; dx++) {
                    int xi = dy * XPITCH + dx;
                    unsigned long long xa = xr[xi];
                    unsigned long long xb = xr[xi + 32];
                    unsigned long long xc = xr[xi + 64];
                    unsigned long long xd = xr[xi + 96];
                    const unsigned long long* wt = &wr[(dy * 3 + dx) * EOC];
                    #pragma unroll
                    for (int op = 0; op < EOC / 2; op++) {
                        ulonglong2 w2 = *(const ulonglong2*)&wt[2 * op];   // LDS.128 broadcast
                        fma2(acc[2 * op][0], xa, w2.x);
                        fma2(acc[2 * op][1], xb, w2.x);
                        fma2(acc[2 * op][2], xc, w2.x);
                        fma2(acc[2 * op][3], xd, w2.x);
                        fma2(acc[2 * op + 1][0], xa, w2.y);
                        fma2(acc[2 * op + 1][1], xb, w2.y);
                        fma2(acc[2 * op + 1][2], xc, w2.y);
                        fma2(acc[2 * op + 1][3], xd, w2.y);
                    }
                }
            }
        }
    }

    // ---- epilogue ----
    if (CONV1) {
        #pragma unroll
        for (int cc = 0; cc < 2; cc++) {
            int c = cch * 2 + cc;
            float bll = bias[0 * CGRP + c];
            float blh = bias[1 * CGRP + c];
            float bhl = bias[2 * CGRP + c];
            float bhh = bias[3 * CGRP + c];
            #pragma unroll
            for (int p = 0; p < NPAIR; p++) {
                #pragma unroll
                for (int hp = 0; hp < 2; hp++) {
                    float ll = (hp ? hiF(acc[0 * 2 + cc][p]) : loF(acc[0 * 2 + cc][p])) + bll;
                    float lh = (hp ? hiF(acc[1 * 2 + cc][p]) : loF(acc[1 * 2 + cc][p])) + blh;
                    float hl = (hp ? hiF(acc[2 * 2 + cc][p]) : loF(acc[2 * 2 + cc][p])) + bhl;
                    float hh = (hp ? hiF(acc[3 * 2 + cc][p]) : loF(acc[3 * 2 + cc][p])) + bhh;
                    float ee = 0.5f * (ll + lh + hl + hh);
                    float eo = 0.5f * (ll - lh + hl - hh);
                    float oe = 0.5f * (ll + lh - hl - hh);
                    float oo = 0.5f * (ll - lh - hl + hh);
                    int sbrow = gh0 + ty;
                    int sbcol = gw0 + tx + 32 * p + 16 * hp;
                    size_t base = (((size_t)b * CGRP + c) * H2 + 2 * sbrow) * W2 + 2 * sbcol;
                    *(float2*)&out[base]      = make_float2(ee, eo);
                    *(float2*)&out[base + W2] = make_float2(oe, oo);
                }
            }
        }
    } else {
        #pragma unroll
        for (int o = 0; o < EOC; o++) {
            int c = cch * EOC + o;
            float bv = bias[c];
            size_t rowbase = (((size_t)b * CGRP + c) * H2 + (gh0 + ty)) * W2 + gw0;
            #pragma unroll
            for (int p = 0; p < NPAIR; p++) {
                #pragma unroll
                for (int hp = 0; hp < 2; hp++) {
                    float v = (hp ? hiF(acc[o][p]) : loF(acc[o][p])) + bv;
                    out[rowbase + tx + 32 * p + 16 * hp] = v;
                }
            }
        }
    }
}

extern "C" void kernel_launch(void* const* d_in, const int* in_sizes, int n_in,
                              void* d_out, int out_size)
{
    const float* x      = (const float*)d_in[0];
    const float* w_pre  = (const float*)d_in[1];
    const float* b_pre  = (const float*)d_in[2];
    const float* w_post = (const float*)d_in[3];
    const float* b_post = (const float*)d_in[4];
    float* out = (float*)d_out;

    float* up = nullptr;
    cudaGetSymbolAddress((void**)&up, g_up);

    size_t smem = (size_t)(CIN * 9 * EOC) * 8 + (size_t)CICHUNK * XROWS * XPITCH * 8;  // 103,680 B
    cudaFuncSetAttribute(conv_kernel<true>,  cudaFuncAttributeMaxDynamicSharedMemorySize, (int)smem);
    cudaFuncSetAttribute(conv_kernel<false>, cudaFuncAttributeMaxDynamicSharedMemorySize, (int)smem);

    dim3 blk(THREADS);
    // conv1: 1 col-tile * 32 c-chunks (2 ch each, 4 groups), 8 row tiles, 16 batches
    dim3 g1((W1 / TW) * (CGRP / 2), H1 / TH, B_);
    conv_kernel<true><<<g1, blk, smem>>>(x, w_pre, b_pre, up);
    // conv2: 2 col-tiles * 8 c-chunks, 16 row tiles, 16 batches
    dim3 g2((W2 / TW) * (CGRP / EOC), H2 / TH, B_);
    conv_kernel<false><<<g2, blk, smem>>>(up, w_post, b_post, out);
}

// round 4
// speedup vs baseline: 6.6749x; 5.8620x over previous
#include <cuda_runtime.h>
#include <cuda_bf16.h>
#include <cstdint>

// ---------------- problem constants ----------------
#define BB    16
#define H1    128
#define W1    128
#define H2    256
#define W2    256

// ---------------- scratch ----------------
__device__ __align__(16) __nv_bfloat16 g_xt[(size_t)BB * H1 * W1 * 128];   // x NHWC hi|lo
__device__ __align__(16) __nv_bfloat16 g_up[(size_t)BB * H2 * W2 * 128];   // upsampled NHWC hi|lo
__device__ __align__(16) __nv_bfloat16 g_wt1[(size_t)9 * 256 * 128];       // conv1 weights [tap][n][128]
__device__ __align__(16) __nv_bfloat16 g_wt2[(size_t)9 * 64 * 128];        // conv2 weights

// smem geometry (bytes)
#define APITCH   272
#define PATCHROW 390
#define PATCH_BYTES (PATCHROW * APITCH)          // 106,080
#define BBUF_OFF PATCH_BYTES
#define STPITCH  133                              // staging pitch (floats)

__device__ __forceinline__ uint32_t smem_u32(const void* p) {
    uint32_t a;
    asm("{ .reg .u64 t; cvta.to.shared.u64 t, %1; cvt.u32.u64 %0, t; }" : "=r"(a) : "l"(p));
    return a;
}

#define LDSM4(r, a) \
    asm volatile("ldmatrix.sync.aligned.m8n8.x4.shared.b16 {%0,%1,%2,%3}, [%4];" \
        : "=r"((r)[0]), "=r"((r)[1]), "=r"((r)[2]), "=r"((r)[3]) : "r"(a))
#define LDSM2(r, a) \
    asm volatile("ldmatrix.sync.aligned.m8n8.x2.shared.b16 {%0,%1}, [%2];" \
        : "=r"((r)[0]), "=r"((r)[1]) : "r"(a))
#define MMA(c, a, b) \
    asm volatile("mma.sync.aligned.m16n8k16.row.col.f32.bf16.bf16.f32 " \
        "{%0,%1,%2,%3},{%4,%5,%6,%7},{%8,%9},{%0,%1,%2,%3};" \
        : "+f"((c)[0]), "+f"((c)[1]), "+f"((c)[2]), "+f"((c)[3]) \
        : "r"((a)[0]), "r"((a)[1]), "r"((a)[2]), "r"((a)[3]), "r"((b)[0]), "r"((b)[1]))
#define CPASYNC(dst, src) \
    asm volatile("cp.async.cg.shared.global [%0], [%1], 16;" :: "r"(dst), "l"(src))
#define CPCOMMIT() asm volatile("cp.async.commit_group;")

union BF8 { __nv_bfloat16 h[8]; uint4 v; };

// ---------------- prep: x NCHW fp32 -> NHWC [hi(64)|lo(64)] bf16 ----------------
__global__ void prep_x(const float* __restrict__ x, __nv_bfloat16* __restrict__ xt) {
    __shared__ float s[64][33];
    int lane = threadIdx.x & 31, ty = threadIdx.x >> 5;
    int w0 = blockIdx.x * 32, h = blockIdx.y, b = blockIdx.z;
    #pragma unroll
    for (int i = 0; i < 8; i++) {
        int ci = i * 8 + ty;
        s[ci][lane] = x[(((size_t)b * 64 + ci) * H1 + h) * W1 + w0 + lane];
    }
    __syncthreads();
    int wp = threadIdx.x >> 3, seg = threadIdx.x & 7;
    BF8 hi, lo;
    #pragma unroll
    for (int j = 0; j < 8; j++) {
        float v = s[seg * 8 + j][wp];
        __nv_bfloat16 hb = __float2bfloat16(v);
        hi.h[j] = hb;
        lo.h[j] = __float2bfloat16(v - __bfloat162float(hb));
    }
    size_t base = (((size_t)b * H1 + h) * W1 + (w0 + wp)) * 128;
    *(uint4*)&xt[base + seg * 8]      = hi.v;
    *(uint4*)&xt[base + 64 + seg * 8] = lo.v;
}

// ---------------- prep: weights OIHW -> [tap][n][hi64|lo64] ----------------
// conv1 n-order: n = cch*128 + (g*32 + cc)  ->  oc = g*64 + cch*32 + cc
__global__ void prep_w(const float* __restrict__ w, __nv_bfloat16* __restrict__ wt,
                       int NT, int conv1) {
    int idx = blockIdx.x * 256 + threadIdx.x;
    if (idx >= 9 * NT * 64) return;
    int ci = idx & 63;
    int rem = idx >> 6;
    int n = rem % NT, tap = rem / NT;
    int oc;
    if (conv1) {
        int cch = n >> 7, nl = n & 127;
        oc = ((nl >> 5) << 6) + (cch << 5) + (nl & 31);
    } else oc = n;
    float v = w[((size_t)oc * 64 + ci) * 9 + tap];
    __nv_bfloat16 hb = __float2bfloat16(v);
    wt[((size_t)tap * NT + n) * 128 + ci]      = hb;
    wt[((size_t)tap * NT + n) * 128 + 64 + ci] = __float2bfloat16(v - __bfloat162float(hb));
}

// ---------------- implicit-GEMM conv via mma.sync (bf16 hi/lo, fp32 acc) ----------------
// M=128 pixels (one row segment), N = NTILES*32 channels. 8 warps = 2(M) x 4(N).
template<int NTILES, bool CONV1>
__global__ void __launch_bounds__(256)
gemm_conv(const __nv_bfloat16* __restrict__ xin,
          const __nv_bfloat16* __restrict__ wt,
          const float* __restrict__ bias,
          float* __restrict__ out,            // conv2 only
          __nv_bfloat16* __restrict__ up)     // conv1 only
{
    constexpr int MTILES = 4;
    constexpr int NT     = NTILES * 8 * 4;    // CTA N (128 or 64)
    constexpr int NTOT   = CONV1 ? 256 : 64;
    constexpr int BBYTES = NT * APITCH;
    const int Hin = CONV1 ? H1 : H2;
    const int Win = CONV1 ? W1 : W2;

    extern __shared__ __align__(16) char smem[];
    const uint32_t sb = smem_u32(smem);
    const int tid = threadIdx.x, wid = tid >> 5, lane = tid & 31;
    const int wm = wid >> 2, wn = wid & 3;

    const int cch = CONV1 ? (int)blockIdx.x : 0;
    const int w0  = CONV1 ? 0 : (int)blockIdx.x * 128;
    const int h0  = blockIdx.y, b = blockIdx.z;
    const int nbase_g = CONV1 ? cch * 128 : 0;

    // ---- A patch load: 390 rows x 256B (zero-filled at borders), pitch 272 ----
    {
        const uint4* src = (const uint4*)xin;
        for (int i = tid; i < PATCHROW * 16; i += 256) {
            int row = i >> 4, c16 = i & 15;
            int hh = row / 130, ww = row - hh * 130;
            int gh = h0 - 1 + hh, gw = w0 - 1 + ww;
            uint4 v = make_uint4(0, 0, 0, 0);
            if (gh >= 0 && gh < Hin && gw >= 0 && gw < Win)
                v = src[((size_t)(b * Hin + gh) * Win + gw) * 16 + c16];
            *(uint4*)(smem + row * APITCH + c16 * 16) = v;
        }
    }
    // ---- prefetch B(tap 0) ----
    {
        const char* wg = (const char*)wt;
        for (int i = tid; i < NT * 16; i += 256) {
            int n = i >> 4, c = i & 15;
            CPASYNC(sb + BBUF_OFF + n * APITCH + c * 16,
                    wg + (((size_t)0 * NTOT + nbase_g + n) * 256) + c * 16);
        }
        CPCOMMIT();
    }

    float acc[MTILES][NTILES][4];
    #pragma unroll
    for (int mt = 0; mt < MTILES; mt++)
        #pragma unroll
        for (int nt = 0; nt < NTILES; nt++)
            #pragma unroll
            for (int q = 0; q < 4; q++) acc[mt][nt][q] = 0.0f;

    const uint32_t aLaneRow = (lane & 15);
    const uint32_t aLaneK   = (lane >> 4) * 16;
    const uint32_t bLaneRow = (lane & 7);
    const uint32_t bLaneK   = ((lane >> 3) & 1) * 16;

    #pragma unroll 1
    for (int tap = 0; tap < 9; tap++) {
        __syncthreads();
        if (tap < 8) {
            const char* wg = (const char*)wt;
            uint32_t dbuf = sb + BBUF_OFF + ((tap + 1) & 1) * BBYTES;
            for (int i = tid; i < NT * 16; i += 256) {
                int n = i >> 4, c = i & 15;
                CPASYNC(dbuf + n * APITCH + c * 16,
                        wg + (((size_t)(tap + 1) * NTOT + nbase_g + n) * 256) + c * 16);
            }
            CPCOMMIT();
            asm volatile("cp.async.wait_group 1;");
        } else {
            asm volatile("cp.async.wait_group 0;");
        }
        __syncthreads();

        const int taprow = (tap / 3) * 130 + (tap % 3);
        const uint32_t aB = sb + (taprow + wm * 64 + aLaneRow) * APITCH + aLaneK;
        const uint32_t bB = sb + BBUF_OFF + (tap & 1) * BBYTES
                          + (wn * NTILES * 8 + bLaneRow) * APITCH + bLaneK;

        #pragma unroll
        for (int ks = 0; ks < 4; ks++) {
            uint32_t aH[MTILES][4], aL[MTILES][4], bH[NTILES][2], bL[NTILES][2];
            #pragma unroll
            for (int mt = 0; mt < MTILES; mt++) LDSM4(aH[mt], aB + mt * 16 * APITCH + ks * 32);
            #pragma unroll
            for (int nt = 0; nt < NTILES; nt++) LDSM2(bH[nt], bB + nt * 8 * APITCH + ks * 32);
            #pragma unroll
            for (int mt = 0; mt < MTILES; mt++)
                #pragma unroll
                for (int nt = 0; nt < NTILES; nt++) MMA(acc[mt][nt], aH[mt], bH[nt]);
            #pragma unroll
            for (int nt = 0; nt < NTILES; nt++) LDSM2(bL[nt], bB + nt * 8 * APITCH + 128 + ks * 32);
            #pragma unroll
            for (int mt = 0; mt < MTILES; mt++)
                #pragma unroll
                for (int nt = 0; nt < NTILES; nt++) MMA(acc[mt][nt], aH[mt], bL[nt]);
            #pragma unroll
            for (int mt = 0; mt < MTILES; mt++) LDSM4(aL[mt], aB + mt * 16 * APITCH + 128 + ks * 32);
            #pragma unroll
            for (int mt = 0; mt < MTILES; mt++)
                #pragma unroll
                for (int nt = 0; nt < NTILES; nt++) MMA(acc[mt][nt], aL[mt], bH[nt]);
        }
    }

    // ---- epilogue: stage (n,m) fp32 + bias into smem (reuse patch area) ----
    __syncthreads();
    float* st = (float*)smem;
    #pragma unroll
    for (int mt = 0; mt < MTILES; mt++)
        #pragma unroll
        for (int nt = 0; nt < NTILES; nt++) {
            int nl = wn * NTILES * 8 + nt * 8 + (lane & 3) * 2;
            int m  = wm * 64 + mt * 16 + (lane >> 2);
            float bv0, bv1;
            if (CONV1) {
                int oc0 = ((nl >> 5) << 6) + (cch << 5) + (nl & 31);
                bv0 = __ldg(&bias[oc0]);
                bv1 = __ldg(&bias[oc0 + 1]);
            } else {
                bv0 = __ldg(&bias[nl]);
                bv1 = __ldg(&bias[nl + 1]);
            }
            st[(nl + 0) * STPITCH + m]     = acc[mt][nt][0] + bv0;
            st[(nl + 1) * STPITCH + m]     = acc[mt][nt][1] + bv1;
            st[(nl + 0) * STPITCH + m + 8] = acc[mt][nt][2] + bv0;
            st[(nl + 1) * STPITCH + m + 8] = acc[mt][nt][3] + bv1;
        }
    __syncthreads();

    if (CONV1) {
        // wavelet mix + bf16 hi/lo split, write upsampled NHWC
        #pragma unroll
        for (int it = 0; it < 2; it++) {
            int item = it * 256 + tid;          // 512 items: m(128) x oct(4)
            int m = item >> 2, oct = item & 3;
            float vll[8], vlh[8], vhl[8], vhh[8];
            #pragma unroll
            for (int j = 0; j < 8; j++) {
                int r = oct * 8 + j;
                vll[j] = st[(r)      * STPITCH + m];
                vlh[j] = st[(r + 32) * STPITCH + m];
                vhl[j] = st[(r + 64) * STPITCH + m];
                vhh[j] = st[(r + 96) * STPITCH + m];
            }
            BF8 hi[4], lo[4];
            #pragma unroll
            for (int j = 0; j < 8; j++) {
                float ee = 0.5f * (vll[j] + vlh[j] + vhl[j] + vhh[j]);
                float eo = 0.5f * (vll[j] - vlh[j] + vhl[j] - vhh[j]);
                float oe = 0.5f * (vll[j] + vlh[j] - vhl[j] - vhh[j]);
                float oo = 0.5f * (vll[j] - vlh[j] - vhl[j] + vhh[j]);
                float q[4] = {ee, eo, oe, oo};
                #pragma unroll
                for (int p = 0; p < 4; p++) {
                    __nv_bfloat16 hb = __float2bfloat16(q[p]);
                    hi[p].h[j] = hb;
                    lo[p].h[j] = __float2bfloat16(q[p] - __bfloat162float(hb));
                }
            }
            int ccb = cch * 32 + oct * 8;
            #pragma unroll
            for (int p = 0; p < 4; p++) {
                int dy = p >> 1, dx = p & 1;
                size_t px = ((size_t)(b * H2 + 2 * h0 + dy) * W2 + 2 * m + dx) * 128;
                *(uint4*)&up[px + ccb]      = hi[p].v;
                *(uint4*)&up[px + 64 + ccb] = lo[p].v;
            }
        }
    } else {
        for (int i = tid; i < 64 * 128; i += 256) {
            int n = i >> 7, m = i & 127;
            out[((size_t)(b * 64 + n) * H2 + h0) * W2 + w0 + m] = st[n * STPITCH + m];
        }
    }
}

// ---------------- launch ----------------
extern "C" void kernel_launch(void* const* d_in, const int* in_sizes, int n_in,
                              void* d_out, int out_size)
{
    const float* x      = (const float*)d_in[0];
    const float* w_pre  = (const float*)d_in[1];
    const float* b_pre  = (const float*)d_in[2];
    const float* w_post = (const float*)d_in[3];
    const float* b_post = (const float*)d_in[4];
    float* out = (float*)d_out;

    __nv_bfloat16 *xt, *up, *wt1, *wt2;
    cudaGetSymbolAddress((void**)&xt,  g_xt);
    cudaGetSymbolAddress((void**)&up,  g_up);
    cudaGetSymbolAddress((void**)&wt1, g_wt1);
    cudaGetSymbolAddress((void**)&wt2, g_wt2);

    const int smem1 = PATCH_BYTES + 2 * 128 * APITCH;   // 175,712
    const int smem2 = PATCH_BYTES + 2 * 64 * APITCH;    // 140,896
    cudaFuncSetAttribute(gemm_conv<4, true>,  cudaFuncAttributeMaxDynamicSharedMemorySize, smem1);
    cudaFuncSetAttribute(gemm_conv<2, false>, cudaFuncAttributeMaxDynamicSharedMemorySize, smem2);

    prep_x<<<dim3(4, 128, 16), 256>>>(x, xt);
    prep_w<<<(9 * 256 * 64 + 255) / 256, 256>>>(w_pre, wt1, 256, 1);
    prep_w<<<(9 * 64 * 64 + 255) / 256, 256>>>(w_post, wt2, 64, 0);

    gemm_conv<4, true><<<dim3(2, 128, 16), 256, smem1>>>(xt, wt1, b_pre, nullptr, up);
    gemm_conv<2, false><<<dim3(2, 256, 16), 256, smem2>>>(up, wt2, b_post, out, nullptr);
}

// round 5
// speedup vs baseline: 8.8444x; 1.3250x over previous
#include <cuda_runtime.h>
#include <cuda_bf16.h>
#include <cstdint>

// ---------------- problem constants ----------------
#define BB    16
#define H1    128
#define W1    128
#define H2    256
#define W2    256

// ---------------- scratch ----------------
__device__ __align__(16) __nv_bfloat16 g_xt[(size_t)BB * H1 * W1 * 128];   // x NHWC hi|lo
__device__ __align__(16) __nv_bfloat16 g_up[(size_t)BB * H2 * W2 * 128];   // upsampled NHWC hi|lo
__device__ __align__(16) __nv_bfloat16 g_wt1[(size_t)9 * 256 * 128];       // conv1 weights [tap][n][128]
__device__ __align__(16) __nv_bfloat16 g_wt2[(size_t)9 * 64 * 128];        // conv2 weights

// smem geometry (bytes)
#define APITCH   272
#define PATCHROW 520                               // 4 input rows x 130 cols
#define PATCH_BYTES (PATCHROW * APITCH)            // 141,440
#define BBUF_OFF PATCH_BYTES
#define STPITCH  260                               // staging pitch (floats), M=256
#define NTHREADS 512

__device__ __forceinline__ uint32_t smem_u32(const void* p) {
    uint32_t a;
    asm("{ .reg .u64 t; cvta.to.shared.u64 t, %1; cvt.u32.u64 %0, t; }" : "=r"(a) : "l"(p));
    return a;
}

#define LDSM4(r, a) \
    asm volatile("ldmatrix.sync.aligned.m8n8.x4.shared.b16 {%0,%1,%2,%3}, [%4];" \
        : "=r"((r)[0]), "=r"((r)[1]), "=r"((r)[2]), "=r"((r)[3]) : "r"(a))
#define LDSM2(r, a) \
    asm volatile("ldmatrix.sync.aligned.m8n8.x2.shared.b16 {%0,%1}, [%2];" \
        : "=r"((r)[0]), "=r"((r)[1]) : "r"(a))
#define MMA(c, a, b) \
    asm volatile("mma.sync.aligned.m16n8k16.row.col.f32.bf16.bf16.f32 " \
        "{%0,%1,%2,%3},{%4,%5,%6,%7},{%8,%9},{%0,%1,%2,%3};" \
        : "+f"((c)[0]), "+f"((c)[1]), "+f"((c)[2]), "+f"((c)[3]) \
        : "r"((a)[0]), "r"((a)[1]), "r"((a)[2]), "r"((a)[3]), "r"((b)[0]), "r"((b)[1]))
#define CPASYNC(dst, src) \
    asm volatile("cp.async.cg.shared.global [%0], [%1], 16;" :: "r"(dst), "l"(src))
#define CPASYNC_Z(dst, src, sz) \
    asm volatile("cp.async.cg.shared.global [%0], [%1], 16, %2;" :: "r"(dst), "l"(src), "r"(sz))
#define CPCOMMIT() asm volatile("cp.async.commit_group;")

union BF8 { __nv_bfloat16 h[8]; uint4 v; };

// ---------------- prep: x NCHW fp32 -> NHWC [hi(64)|lo(64)] bf16 ----------------
__global__ void prep_x(const float* __restrict__ x, __nv_bfloat16* __restrict__ xt) {
    __shared__ float s[64][33];
    int lane = threadIdx.x & 31, ty = threadIdx.x >> 5;
    int w0 = blockIdx.x * 32, h = blockIdx.y, b = blockIdx.z;
    #pragma unroll
    for (int i = 0; i < 8; i++) {
        int ci = i * 8 + ty;
        s[ci][lane] = x[(((size_t)b * 64 + ci) * H1 + h) * W1 + w0 + lane];
    }
    __syncthreads();
    int wp = threadIdx.x >> 3, seg = threadIdx.x & 7;
    BF8 hi, lo;
    #pragma unroll
    for (int j = 0; j < 8; j++) {
        float v = s[seg * 8 + j][wp];
        __nv_bfloat16 hb = __float2bfloat16(v);
        hi.h[j] = hb;
        lo.h[j] = __float2bfloat16(v - __bfloat162float(hb));
    }
    size_t base = (((size_t)b * H1 + h) * W1 + (w0 + wp)) * 128;
    *(uint4*)&xt[base + seg * 8]      = hi.v;
    *(uint4*)&xt[base + 64 + seg * 8] = lo.v;
}

// ---------------- prep: weights OIHW -> [tap][n][hi64|lo64] ----------------
__global__ void prep_w(const float* __restrict__ w, __nv_bfloat16* __restrict__ wt,
                       int NT, int conv1) {
    int idx = blockIdx.x * 256 + threadIdx.x;
    if (idx >= 9 * NT * 64) return;
    int ci = idx & 63;
    int rem = idx >> 6;
    int n = rem % NT, tap = rem / NT;
    int oc;
    if (conv1) {
        int cch = n >> 7, nl = n & 127;
        oc = ((nl >> 5) << 6) + (cch << 5) + (nl & 31);
    } else oc = n;
    float v = w[((size_t)oc * 64 + ci) * 9 + tap];
    __nv_bfloat16 hb = __float2bfloat16(v);
    wt[((size_t)tap * NT + n) * 128 + ci]      = hb;
    wt[((size_t)tap * NT + n) * 128 + 64 + ci] = __float2bfloat16(v - __bfloat162float(hb));
}

// ---------------- implicit-GEMM conv via mma.sync, M=256 (row pair), 512 thr ----------------
template<int NTILES, bool CONV1>
__global__ void __launch_bounds__(NTHREADS)
gemm_conv(const __nv_bfloat16* __restrict__ xin,
          const __nv_bfloat16* __restrict__ wt,
          const float* __restrict__ bias,
          float* __restrict__ out,            // conv2 only
          __nv_bfloat16* __restrict__ up)     // conv1 only
{
    constexpr int MTILES = 4;
    constexpr int NT     = NTILES * 8 * 4;    // 128 (conv1) or 64 (conv2)
    constexpr int NTOT   = CONV1 ? 256 : 64;
    constexpr int BBYTES = NT * APITCH;
    const int Hin = CONV1 ? H1 : H2;
    const int Win = CONV1 ? W1 : W2;

    extern __shared__ __align__(16) char smem[];
    const uint32_t sb = smem_u32(smem);
    const int tid = threadIdx.x, wid = tid >> 5, lane = tid & 31;
    const int wm = wid >> 2, wn = wid & 3;       // 4 x 4 warp grid
    const int wrow = wm >> 1;                    // output local row 0/1
    const int wcol = (wm & 1) * 64;              // col base within row

    const int cch = CONV1 ? (int)blockIdx.x : 0;
    const int w0  = CONV1 ? 0 : (int)blockIdx.x * 128;
    const int h0  = blockIdx.y * 2;              // input row pair base
    const int b   = blockIdx.z;
    const int nbase_g = CONV1 ? cch * 128 : 0;

    // ---- A patch: 4 rows x 130 cols x 256B, cp.async with zero-fill ----
    {
        for (int i = tid; i < PATCHROW * 16; i += NTHREADS) {
            int row = i >> 4, c16 = i & 15;
            int hh = row / 130, ww = row - hh * 130;
            int gh = h0 - 1 + hh, gw = w0 - 1 + ww;
            bool ok = (gh >= 0 && gh < Hin && gw >= 0 && gw < Win);
            const char* src = (const char*)xin
                + (ok ? (((size_t)(b * Hin + (ok ? gh : 0)) * Win + (ok ? gw : 0)) * 256 + c16 * 16) : 0);
            CPASYNC_Z(sb + row * APITCH + c16 * 16, src, ok ? 16 : 0);
        }
    }
    // ---- prefetch B(tap 0), same commit group as patch ----
    {
        const char* wg = (const char*)wt;
        for (int i = tid; i < NT * 16; i += NTHREADS) {
            int n = i >> 4, c = i & 15;
            CPASYNC(sb + BBUF_OFF + n * APITCH + c * 16,
                    wg + (((size_t)0 * NTOT + nbase_g + n) * 256) + c * 16);
        }
        CPCOMMIT();
    }

    float acc[MTILES][NTILES][4];
    #pragma unroll
    for (int mt = 0; mt < MTILES; mt++)
        #pragma unroll
        for (int nt = 0; nt < NTILES; nt++)
            #pragma unroll
            for (int q = 0; q < 4; q++) acc[mt][nt][q] = 0.0f;

    const uint32_t aLaneRow = (lane & 15);
    const uint32_t aLaneK   = (lane >> 4) * 16;
    const uint32_t bLaneRow = (lane & 7);
    const uint32_t bLaneK   = ((lane >> 3) & 1) * 16;

    #pragma unroll 1
    for (int tap = 0; tap < 9; tap++) {
        __syncthreads();                       // all warps done reading buffer being overwritten
        if (tap < 8) {
            const char* wg = (const char*)wt;
            uint32_t dbuf = sb + BBUF_OFF + ((tap + 1) & 1) * BBYTES;
            for (int i = tid; i < NT * 16; i += NTHREADS) {
                int n = i >> 4, c = i & 15;
                CPASYNC(dbuf + n * APITCH + c * 16,
                        wg + (((size_t)(tap + 1) * NTOT + nbase_g + n) * 256) + c * 16);
            }
            CPCOMMIT();
            asm volatile("cp.async.wait_group 1;");
        } else {
            asm volatile("cp.async.wait_group 0;");
        }
        __syncthreads();

        const int dy = tap / 3, dx = tap % 3;
        const uint32_t aB = sb + (uint32_t)(((wrow + dy) * 130 + dx + wcol + aLaneRow) * APITCH) + aLaneK;
        const uint32_t bB = sb + BBUF_OFF + (tap & 1) * BBYTES
                          + (wn * NTILES * 8 + bLaneRow) * APITCH + bLaneK;

        #pragma unroll
        for (int ks = 0; ks < 4; ks++) {
            uint32_t aH[MTILES][4], aL[MTILES][4], bH[NTILES][2], bL[NTILES][2];
            #pragma unroll
            for (int mt = 0; mt < MTILES; mt++) LDSM4(aH[mt], aB + mt * 16 * APITCH + ks * 32);
            #pragma unroll
            for (int nt = 0; nt < NTILES; nt++) LDSM2(bH[nt], bB + nt * 8 * APITCH + ks * 32);
            #pragma unroll
            for (int mt = 0; mt < MTILES; mt++)
                #pragma unroll
                for (int nt = 0; nt < NTILES; nt++) MMA(acc[mt][nt], aH[mt], bH[nt]);
            #pragma unroll
            for (int nt = 0; nt < NTILES; nt++) LDSM2(bL[nt], bB + nt * 8 * APITCH + 128 + ks * 32);
            #pragma unroll
            for (int mt = 0; mt < MTILES; mt++)
                #pragma unroll
                for (int nt = 0; nt < NTILES; nt++) MMA(acc[mt][nt], aH[mt], bL[nt]);
            #pragma unroll
            for (int mt = 0; mt < MTILES; mt++) LDSM4(aL[mt], aB + mt * 16 * APITCH + 128 + ks * 32);
            #pragma unroll
            for (int mt = 0; mt < MTILES; mt++)
                #pragma unroll
                for (int nt = 0; nt < NTILES; nt++) MMA(acc[mt][nt], aL[mt], bH[nt]);
        }
    }

    // ---- stage (n, m) fp32 + bias into smem (reuse patch area) ----
    __syncthreads();
    float* st = (float*)smem;
    #pragma unroll
    for (int mt = 0; mt < MTILES; mt++)
        #pragma unroll
        for (int nt = 0; nt < NTILES; nt++) {
            int nl = wn * NTILES * 8 + nt * 8 + (lane & 3) * 2;
            int m  = wm * 64 + mt * 16 + (lane >> 2);
            float bv0, bv1;
            if (CONV1) {
                int oc0 = ((nl >> 5) << 6) + (cch << 5) + (nl & 31);
                bv0 = __ldg(&bias[oc0]);
                bv1 = __ldg(&bias[oc0 + 1]);
            } else {
                bv0 = __ldg(&bias[nl]);
                bv1 = __ldg(&bias[nl + 1]);
            }
            st[(nl + 0) * STPITCH + m]     = acc[mt][nt][0] + bv0;
            st[(nl + 1) * STPITCH + m]     = acc[mt][nt][1] + bv1;
            st[(nl + 0) * STPITCH + m + 8] = acc[mt][nt][2] + bv0;
            st[(nl + 1) * STPITCH + m + 8] = acc[mt][nt][3] + bv1;
        }
    __syncthreads();

    if (CONV1) {
        // wavelet mix + bf16 hi/lo split, write upsampled NHWC
        #pragma unroll
        for (int it = 0; it < 2; it++) {
            int item = it * NTHREADS + tid;        // 1024 items: m(256) x oct(4)
            int m = item >> 2, oct = item & 3;
            int mr = m >> 7, mc = m & 127;
            float vll[8], vlh[8], vhl[8], vhh[8];
            #pragma unroll
            for (int j = 0; j < 8; j++) {
                int r = oct * 8 + j;
                vll[j] = st[(r)      * STPITCH + m];
                vlh[j] = st[(r + 32) * STPITCH + m];
                vhl[j] = st[(r + 64) * STPITCH + m];
                vhh[j] = st[(r + 96) * STPITCH + m];
            }
            BF8 hi[4], lo[4];
            #pragma unroll
            for (int j = 0; j < 8; j++) {
                float ee = 0.5f * (vll[j] + vlh[j] + vhl[j] + vhh[j]);
                float eo = 0.5f * (vll[j] - vlh[j] + vhl[j] - vhh[j]);
                float oe = 0.5f * (vll[j] + vlh[j] - vhl[j] - vhh[j]);
                float oo = 0.5f * (vll[j] - vlh[j] - vhl[j] + vhh[j]);
                float q[4] = {ee, eo, oe, oo};
                #pragma unroll
                for (int p = 0; p < 4; p++) {
                    __nv_bfloat16 hb = __float2bfloat16(q[p]);
                    hi[p].h[j] = hb;
                    lo[p].h[j] = __float2bfloat16(q[p] - __bfloat162float(hb));
                }
            }
            int ccb = cch * 32 + oct * 8;
            #pragma unroll
            for (int p = 0; p < 4; p++) {
                int dy = p >> 1, dx = p & 1;
                size_t px = ((size_t)(b * H2 + 2 * (h0 + mr) + dy) * W2 + 2 * mc + dx) * 128;
                *(uint4*)&up[px + ccb]      = hi[p].v;
                *(uint4*)&up[px + 64 + ccb] = lo[p].v;
            }
        }
    } else {
        for (int i = tid; i < 64 * 256; i += NTHREADS) {
            int n = i >> 8, m = i & 255;
            out[((size_t)(b * 64 + n) * H2 + h0 + (m >> 7)) * W2 + w0 + (m & 127)] = st[n * STPITCH + m];
        }
    }
}

// ---------------- launch ----------------
extern "C" void kernel_launch(void* const* d_in, const int* in_sizes, int n_in,
                              void* d_out, int out_size)
{
    const float* x      = (const float*)d_in[0];
    const float* w_pre  = (const float*)d_in[1];
    const float* b_pre  = (const float*)d_in[2];
    const float* w_post = (const float*)d_in[3];
    const float* b_post = (const float*)d_in[4];
    float* out = (float*)d_out;

    __nv_bfloat16 *xt, *up, *wt1, *wt2;
    cudaGetSymbolAddress((void**)&xt,  g_xt);
    cudaGetSymbolAddress((void**)&up,  g_up);
    cudaGetSymbolAddress((void**)&wt1, g_wt1);
    cudaGetSymbolAddress((void**)&wt2, g_wt2);

    const int smem1 = PATCH_BYTES + 2 * 128 * APITCH;   // 211,072
    const int smem2 = PATCH_BYTES + 2 * 64 * APITCH;    // 176,256
    cudaFuncSetAttribute(gemm_conv<4, true>,  cudaFuncAttributeMaxDynamicSharedMemorySize, smem1);
    cudaFuncSetAttribute(gemm_conv<2, false>, cudaFuncAttributeMaxDynamicSharedMemorySize, smem2);

    prep_x<<<dim3(4, 128, 16), 256>>>(x, xt);
    prep_w<<<(9 * 256 * 64 + 255) / 256, 256>>>(w_pre, wt1, 256, 1);
    prep_w<<<(9 * 64 * 64 + 255) / 256, 256>>>(w_post, wt2, 64, 0);

    gemm_conv<4, true><<<dim3(2, 64, 16), NTHREADS, smem1>>>(xt, wt1, b_pre, nullptr, up);
    gemm_conv<2, false><<<dim3(2, 128, 16), NTHREADS, smem2>>>(up, wt2, b_post, out, nullptr);
}

// round 8
// speedup vs baseline: 8.8711x; 1.0030x over previous
#include <cuda_runtime.h>
#include <cuda_bf16.h>
#include <cstdint>

// ---------------- problem constants ----------------
#define BB    16
#define H1    128
#define W1    128
#define H2    256
#define W2    256

// ---------------- scratch ----------------
__device__ __align__(16) __nv_bfloat16 g_xt[(size_t)BB * H1 * W1 * 128];   // x NHWC hi|lo
__device__ __align__(16) __nv_bfloat16 g_up[(size_t)BB * H2 * W2 * 128];   // upsampled NHWC hi|lo
__device__ __align__(16) __nv_bfloat16 g_wt1[(size_t)9 * 256 * 128];       // conv1 weights [tap][n][128]
__device__ __align__(16) __nv_bfloat16 g_wt2[(size_t)9 * 64 * 128];        // conv2 weights

// smem geometry (bytes)
#define APITCH   272
#define PATCHROW 520                               // 4 input rows x 130 cols
#define PATCH_BYTES (PATCHROW * APITCH)            // 141,440
#define BBUF_OFF PATCH_BYTES
#define STPITCH  260                               // staging pitch (floats), M=256
#define NTHREADS 512

__device__ __forceinline__ uint32_t smem_u32(const void* p) {
    uint32_t a;
    asm("{ .reg .u64 t; cvta.to.shared.u64 t, %1; cvt.u32.u64 %0, t; }" : "=r"(a) : "l"(p));
    return a;
}

#define LDSM4(r, a) \
    asm volatile("ldmatrix.sync.aligned.m8n8.x4.shared.b16 {%0,%1,%2,%3}, [%4];" \
        : "=r"((r)[0]), "=r"((r)[1]), "=r"((r)[2]), "=r"((r)[3]) : "r"(a))
#define MMA(c, a, b) \
    asm volatile("mma.sync.aligned.m16n8k16.row.col.f32.bf16.bf16.f32 " \
        "{%0,%1,%2,%3},{%4,%5,%6,%7},{%8,%9},{%0,%1,%2,%3};" \
        : "+f"((c)[0]), "+f"((c)[1]), "+f"((c)[2]), "+f"((c)[3]) \
        : "r"((a)[0]), "r"((a)[1]), "r"((a)[2]), "r"((a)[3]), "r"((b)[0]), "r"((b)[1]))
#define CPASYNC(dst, src) \
    asm volatile("cp.async.cg.shared.global [%0], [%1], 16;" :: "r"(dst), "l"(src))
#define CPASYNC_Z(dst, src, sz) \
    asm volatile("cp.async.cg.shared.global [%0], [%1], 16, %2;" :: "r"(dst), "l"(src), "r"(sz))
#define CPCOMMIT() asm volatile("cp.async.commit_group;")

union BF8 { __nv_bfloat16 h[8]; uint4 v; };

// ---------------- prep: x NCHW fp32 -> NHWC [hi(64)|lo(64)] bf16 ----------------
__global__ void prep_x(const float* __restrict__ x, __nv_bfloat16* __restrict__ xt) {
    __shared__ float s[64][33];
    int lane = threadIdx.x & 31, ty = threadIdx.x >> 5;
    int w0 = blockIdx.x * 32, h = blockIdx.y, b = blockIdx.z;
    #pragma unroll
    for (int i = 0; i < 8; i++) {
        int ci = i * 8 + ty;
        s[ci][lane] = x[(((size_t)b * 64 + ci) * H1 + h) * W1 + w0 + lane];
    }
    __syncthreads();
    int wp = threadIdx.x >> 3, seg = threadIdx.x & 7;
    BF8 hi, lo;
    #pragma unroll
    for (int j = 0; j < 8; j++) {
        float v = s[seg * 8 + j][wp];
        __nv_bfloat16 hb = __float2bfloat16(v);
        hi.h[j] = hb;
        lo.h[j] = __float2bfloat16(v - __bfloat162float(hb));
    }
    size_t base = (((size_t)b * H1 + h) * W1 + (w0 + wp)) * 128;
    *(uint4*)&xt[base + seg * 8]      = hi.v;
    *(uint4*)&xt[base + 64 + seg * 8] = lo.v;
}

// ---------------- prep: weights OIHW -> [tap][n][hi64|lo64] ----------------
__global__ void prep_w(const float* __restrict__ w, __nv_bfloat16* __restrict__ wt,
                       int NT, int conv1) {
    int idx = blockIdx.x * 256 + threadIdx.x;
    if (idx >= 9 * NT * 64) return;
    int ci = idx & 63;
    int rem = idx >> 6;
    int n = rem % NT, tap = rem / NT;
    int oc;
    if (conv1) {
        int cch = n >> 7, nl = n & 127;
        oc = ((nl >> 5) << 6) + (cch << 5) + (nl & 31);
    } else oc = n;
    float v = w[((size_t)oc * 64 + ci) * 9 + tap];
    __nv_bfloat16 hb = __float2bfloat16(v);
    wt[((size_t)tap * NT + n) * 128 + ci]      = hb;
    wt[((size_t)tap * NT + n) * 128 + 64 + ci] = __float2bfloat16(v - __bfloat162float(hb));
}

// ---------------- implicit-GEMM conv via mma.sync, M=256 (row pair), 512 thr ----------------
template<int NTILES, bool CONV1>
__global__ void __launch_bounds__(NTHREADS)
gemm_conv(const __nv_bfloat16* __restrict__ xin,
          const __nv_bfloat16* __restrict__ wt,
          const float* __restrict__ bias,
          float* __restrict__ out,            // conv2 only
          __nv_bfloat16* __restrict__ up)     // conv1 only
{
    constexpr int MTILES = 4;
    constexpr int NT     = NTILES * 8 * 4;    // 128 (conv1) or 64 (conv2)
    constexpr int NTOT   = CONV1 ? 256 : 64;
    constexpr int BBYTES = NT * APITCH;
    const int Hin = CONV1 ? H1 : H2;
    const int Win = CONV1 ? W1 : W2;

    extern __shared__ __align__(16) char smem[];
    const uint32_t sb = smem_u32(smem);
    const int tid = threadIdx.x, wid = tid >> 5, lane = tid & 31;
    const int wm = wid >> 2, wn = wid & 3;       // 4 x 4 warp grid
    const int wrow = wm >> 1;                    // output local row 0/1
    const int wcol = (wm & 1) * 64;              // col base within row

    const int cch = CONV1 ? (int)blockIdx.x : 0;
    const int w0  = CONV1 ? 0 : (int)blockIdx.x * 128;
    const int h0  = blockIdx.y * 2;              // input row pair base
    const int b   = blockIdx.z;
    const int nbase_g = CONV1 ? cch * 128 : 0;

    // ---- A patch: 4 rows x 130 cols x 256B, cp.async zero-fill; + B(tap0); one group ----
    {
        for (int i = tid; i < PATCHROW * 16; i += NTHREADS) {
            int row = i >> 4, c16 = i & 15;
            int hh = row / 130, ww = row - hh * 130;
            int gh = h0 - 1 + hh, gw = w0 - 1 + ww;
            bool ok = (gh >= 0 && gh < Hin && gw >= 0 && gw < Win);
            const char* src = (const char*)xin
                + (ok ? (((size_t)(b * Hin + (ok ? gh : 0)) * Win + (ok ? gw : 0)) * 256 + c16 * 16) : 0);
            CPASYNC_Z(sb + row * APITCH + c16 * 16, src, ok ? 16 : 0);
        }
        const char* wg = (const char*)wt;
        for (int i = tid; i < NT * 16; i += NTHREADS) {
            int n = i >> 4, c = i & 15;
            CPASYNC(sb + BBUF_OFF + n * APITCH + c * 16,
                    wg + (((size_t)0 * NTOT + nbase_g + n) * 256) + c * 16);
        }
        CPCOMMIT();
    }

    float acc[MTILES][NTILES][4];
    #pragma unroll
    for (int mt = 0; mt < MTILES; mt++)
        #pragma unroll
        for (int nt = 0; nt < NTILES; nt++)
            #pragma unroll
            for (int q = 0; q < 4; q++) acc[mt][nt][q] = 0.0f;

    const uint32_t aLaneRow = (lane & 15);
    const uint32_t aLaneK   = (lane >> 4) * 16;
    // B x4 lane map: lanes 0-15 -> n-tile p0 (rows, then +16B), 16-31 -> n-tile p0+1
    const uint32_t bLaneRow = ((lane >> 4) * 8) + (lane & 7);
    const uint32_t bLaneK   = ((lane >> 3) & 1) * 16;

    #pragma unroll 1
    for (int tap = 0; tap < 9; tap++) {
        asm volatile("cp.async.wait_group 0;");
        __syncthreads();                        // B(tap) visible; all warps done with buf[(tap+1)&1]
        if (tap < 8) {                          // prefetch B(tap+1), overlaps compute(tap)
            const char* wg = (const char*)wt;
            uint32_t dbuf = sb + BBUF_OFF + ((tap + 1) & 1) * BBYTES;
            for (int i = tid; i < NT * 16; i += NTHREADS) {
                int n = i >> 4, c = i & 15;
                CPASYNC(dbuf + n * APITCH + c * 16,
                        wg + (((size_t)(tap + 1) * NTOT + nbase_g + n) * 256) + c * 16);
            }
            CPCOMMIT();
        }

        const int dy = tap / 3, dx = tap % 3;
        const uint32_t aB = sb + (uint32_t)(((wrow + dy) * 130 + dx + wcol + aLaneRow) * APITCH) + aLaneK;
        const uint32_t bB = sb + BBUF_OFF + (tap & 1) * BBYTES
                          + (wn * NTILES * 8 + bLaneRow) * APITCH + bLaneK;

        #pragma unroll
        for (int ks = 0; ks < 4; ks++) {
            uint32_t aH[MTILES][4], aL[MTILES][4];
            uint32_t bH[NTILES * 2], bL[NTILES * 2];   // flat: [nt][2]
            #pragma unroll
            for (int mt = 0; mt < MTILES; mt++) LDSM4(aH[mt], aB + mt * 16 * APITCH + ks * 32);
            #pragma unroll
            for (int p = 0; p < NTILES / 2; p++)
                LDSM4(&bH[4 * p], bB + p * 16 * APITCH + ks * 32);
            #pragma unroll
            for (int mt = 0; mt < MTILES; mt++)
                #pragma unroll
                for (int nt = 0; nt < NTILES; nt++) MMA(acc[mt][nt], aH[mt], &bH[2 * nt]);
            #pragma unroll
            for (int p = 0; p < NTILES / 2; p++)
                LDSM4(&bL[4 * p], bB + p * 16 * APITCH + 128 + ks * 32);
            #pragma unroll
            for (int mt = 0; mt < MTILES; mt++)
                #pragma unroll
                for (int nt = 0; nt < NTILES; nt++) MMA(acc[mt][nt], aH[mt], &bL[2 * nt]);
            #pragma unroll
            for (int mt = 0; mt < MTILES; mt++) LDSM4(aL[mt], aB + mt * 16 * APITCH + 128 + ks * 32);
            #pragma unroll
            for (int mt = 0; mt < MTILES; mt++)
                #pragma unroll
                for (int nt = 0; nt < NTILES; nt++) MMA(acc[mt][nt], aL[mt], &bH[2 * nt]);
        }
    }

    // ---- stage (n, m) fp32 + bias into smem (reuse patch area) ----
    __syncthreads();
    float* st = (float*)smem;
    #pragma unroll
    for (int mt = 0; mt < MTILES; mt++)
        #pragma unroll
        for (int nt = 0; nt < NTILES; nt++) {
            int nl = wn * NTILES * 8 + nt * 8 + (lane & 3) * 2;
            int m  = wm * 64 + mt * 16 + (lane >> 2);
            float bv0, bv1;
            if (CONV1) {
                int oc0 = ((nl >> 5) << 6) + (cch << 5) + (nl & 31);
                bv0 = __ldg(&bias[oc0]);
                bv1 = __ldg(&bias[oc0 + 1]);
            } else {
                bv0 = __ldg(&bias[nl]);
                bv1 = __ldg(&bias[nl + 1]);
            }
            st[(nl + 0) * STPITCH + m]     = acc[mt][nt][0] + bv0;
            st[(nl + 1) * STPITCH + m]     = acc[mt][nt][1] + bv1;
            st[(nl + 0) * STPITCH + m + 8] = acc[mt][nt][2] + bv0;
            st[(nl + 1) * STPITCH + m + 8] = acc[mt][nt][3] + bv1;
        }
    __syncthreads();

    if (CONV1) {
        // wavelet mix + bf16 hi/lo split, write upsampled NHWC
        #pragma unroll
        for (int it = 0; it < 2; it++) {
            int item = it * NTHREADS + tid;        // 1024 items: m(256) x oct(4)
            int m = item >> 2, oct = item & 3;
            int mr = m >> 7, mc = m & 127;
            float vll[8], vlh[8], vhl[8], vhh[8];
            #pragma unroll
            for (int j = 0; j < 8; j++) {
                int r = oct * 8 + j;
                vll[j] = st[(r)      * STPITCH + m];
                vlh[j] = st[(r + 32) * STPITCH + m];
                vhl[j] = st[(r + 64) * STPITCH + m];
                vhh[j] = st[(r + 96) * STPITCH + m];
            }
            BF8 hi[4], lo[4];
            #pragma unroll
            for (int j = 0; j < 8; j++) {
                float ee = 0.5f * (vll[j] + vlh[j] + vhl[j] + vhh[j]);
                float eo = 0.5f * (vll[j] - vlh[j] + vhl[j] - vhh[j]);
                float oe = 0.5f * (vll[j] + vlh[j] - vhl[j] - vhh[j]);
                float oo = 0.5f * (vll[j] - vlh[j] - vhl[j] + vhh[j]);
                float q[4] = {ee, eo, oe, oo};
                #pragma unroll
                for (int p = 0; p < 4; p++) {
                    __nv_bfloat16 hb = __float2bfloat16(q[p]);
                    hi[p].h[j] = hb;
                    lo[p].h[j] = __float2bfloat16(q[p] - __bfloat162float(hb));
                }
            }
            int ccb = cch * 32 + oct * 8;
            #pragma unroll
            for (int p = 0; p < 4; p++) {
                int dy = p >> 1, dx = p & 1;
                size_t px = ((size_t)(b * H2 + 2 * (h0 + mr) + dy) * W2 + 2 * mc + dx) * 128;
                *(uint4*)&up[px + ccb]      = hi[p].v;
                *(uint4*)&up[px + 64 + ccb] = lo[p].v;
            }
        }
    } else {
        for (int i = tid; i < 64 * 256; i += NTHREADS) {
            int n = i >> 8, m = i & 255;
            out[((size_t)(b * 64 + n) * H2 + h0 + (m >> 7)) * W2 + w0 + (m & 127)] = st[n * STPITCH + m];
        }
    }
}

// ---------------- launch ----------------
extern "C" void kernel_launch(void* const* d_in, const int* in_sizes, int n_in,
                              void* d_out, int out_size)
{
    const float* x      = (const float*)d_in[0];
    const float* w_pre  = (const float*)d_in[1];
    const float* b_pre  = (const float*)d_in[2];
    const float* w_post = (const float*)d_in[3];
    const float* b_post = (const float*)d_in[4];
    float* out = (float*)d_out;

    __nv_bfloat16 *xt, *up, *wt1, *wt2;
    cudaGetSymbolAddress((void**)&xt,  g_xt);
    cudaGetSymbolAddress((void**)&up,  g_up);
    cudaGetSymbolAddress((void**)&wt1, g_wt1);
    cudaGetSymbolAddress((void**)&wt2, g_wt2);

    const int smem1 = PATCH_BYTES + 2 * 128 * APITCH;   // 211,072
    const int smem2 = PATCH_BYTES + 2 * 64 * APITCH;    // 176,256
    cudaFuncSetAttribute(gemm_conv<4, true>,  cudaFuncAttributeMaxDynamicSharedMemorySize, smem1);
    cudaFuncSetAttribute(gemm_conv<2, false>, cudaFuncAttributeMaxDynamicSharedMemorySize, smem2);

    prep_x<<<dim3(4, 128, 16), 256>>>(x, xt);
    prep_w<<<(9 * 256 * 64 + 255) / 256, 256>>>(w_pre, wt1, 256, 1);
    prep_w<<<(9 * 64 * 64 + 255) / 256, 256>>>(w_post, wt2, 64, 0);

    gemm_conv<4, true><<<dim3(2, 64, 16), NTHREADS, smem1>>>(xt, wt1, b_pre, nullptr, up);
    gemm_conv<2, false><<<dim3(2, 128, 16), NTHREADS, smem2>>>(up, wt2, b_post, out, nullptr);
}